// round 8
// baseline (speedup 1.0000x reference)
#include <cuda_runtime.h>
#include <math.h>
#include <stdint.h>

// ---------------- static scratch (no allocations allowed) ----------------
#define MAXN 50000
#define MAXE 800000
#define MAXT (MAXN + MAXE)

__device__ int   g_deg[MAXN];
__device__ int   g_off[MAXN + 1];
__device__ int   g_cur[MAXN];
__device__ int   g_srcl[MAXT];
__device__ __align__(16) float g_h[(size_t)MAXN * 256];
__device__ __align__(16) float g_o[(size_t)MAXN * 256];
__device__ __align__(16) float g_as[MAXN * 4];
__device__ __align__(16) float g_ad[MAXN * 4];
__device__ float g_bnsum[256];
__device__ float g_bnsq[256];
__device__ float g_pool[64 * 64];
__device__ float g_cnt[64];

__device__ __forceinline__ float lrelu2(float v) { return v > 0.f ? v : 0.2f * v; }
__device__ __forceinline__ float eluf(float v) { return v > 0.f ? v : (__expf(v) - 1.0f); }
__device__ __forceinline__ unsigned f2tf(float x) {
    unsigned r;
    asm("cvt.rna.tf32.f32 %0, %1;" : "=r"(r) : "f"(x));
    return r;
}

// ---------------- CSR build ----------------
__global__ void kzero_deg(int N) {
    int i = blockIdx.x * blockDim.x + threadIdx.x;
    if (i < N) g_deg[i] = 0;
    if (i < 64 * 64) g_pool[i] = 0.f;
    if (i < 64) g_cnt[i] = 0.f;
}

__global__ void khist(const int* __restrict__ ei, int E, int N) {
    int i = blockIdx.x * blockDim.x + threadIdx.x;
    int T = E + N;
    if (i >= T) return;
    int d = (i < E) ? ei[E + i] : (i - E);
    atomicAdd(&g_deg[d], 1);
}

__global__ void kscan(int N) {
    __shared__ int sh[1024];
    int t = threadIdx.x;
    int chunk = (N + 1023) >> 10;
    int b = t * chunk;
    int e = min(b + chunk, N);
    int s = 0;
    for (int i = b; i < e; i++) s += g_deg[i];
    sh[t] = s;
    __syncthreads();
    for (int off = 1; off < 1024; off <<= 1) {
        int v = (t >= off) ? sh[t - off] : 0;
        __syncthreads();
        sh[t] += v;
        __syncthreads();
    }
    int run = (t == 0) ? 0 : sh[t - 1];
    for (int i = b; i < e; i++) {
        g_off[i] = run;
        g_cur[i] = run;
        run += g_deg[i];
    }
    if (t == 1023) g_off[N] = sh[1023];
}

__global__ void kscatter(const int* __restrict__ ei, int E, int N) {
    int i = blockIdx.x * blockDim.x + threadIdx.x;
    int T = E + N;
    if (i >= T) return;
    int s, d;
    if (i < E) { s = ei[i]; d = ei[E + i]; }
    else       { s = i - E; d = i - E; }
    int pos = atomicAdd(&g_cur[d], 1);
    g_srcl[pos] = s;
}

// ---------------- TF32 tensor-core GEMM: C[M,NT] = A[M,K] @ B[K,NT] (fp32 out) ----------------
template <int BN_, bool FUSE>
__global__ __launch_bounds__(256, 2) void tgemm(
    const float* __restrict__ A, const float* __restrict__ B, float* __restrict__ C,
    int M, int NT, int K,
    const float* __restrict__ gam, const float* __restrict__ bet)
{
    constexpr int BM_ = 128, BK_ = 32;
    constexpr int RA = BK_ + 4;
    constexpr int RB = BN_ + 8;
    constexpr int NU = BN_ / 32;
    constexpr int NBF = BK_ * BN_ / 4 / 256;

    __shared__ unsigned sA[BM_ * RA];
    __shared__ unsigned sB[BK_ * RB];
    __shared__ float ssc[256], ssh[256];

    const int t = threadIdx.x;
    const int lane = t & 31;
    const int wid = t >> 5;
    const int wr = wid >> 2;
    const int wc = wid & 3;
    const int rowBase = blockIdx.y * BM_;
    const int colBase = blockIdx.x * BN_;
    const int mmarow = lane >> 2;
    const int mmak = lane & 3;

    if (FUSE) {
        float invN = 1.0f / (float)M;
        for (int i = t; i < K; i += 256) {
            float mean = g_bnsum[i] * invN;
            float var = g_bnsq[i] * invN - mean * mean;
            float s = rsqrtf(var + 1e-5f) * gam[i];
            ssc[i] = s;
            ssh[i] = bet[i] - mean * s;
        }
    }

    float acc[4][NU][4];
#pragma unroll
    for (int m = 0; m < 4; m++)
#pragma unroll
        for (int u = 0; u < NU; u++)
#pragma unroll
            for (int j = 0; j < 4; j++) acc[m][u][j] = 0.f;

    for (int k0 = 0; k0 < K; k0 += BK_) {
        __syncthreads();
#pragma unroll
        for (int i = 0; i < 4; i++) {
            int f = i * 256 + t;
            int row = f >> 3;
            int c4 = (f & 7) << 2;
            int gr = rowBase + row;
            float4 v = make_float4(0.f, 0.f, 0.f, 0.f);
            if (gr < M) v = *(const float4*)&A[(size_t)gr * K + k0 + c4];
            if (FUSE) {
                int c = k0 + c4;
                v.x = eluf(v.x * ssc[c + 0] + ssh[c + 0]);
                v.y = eluf(v.y * ssc[c + 1] + ssh[c + 1]);
                v.z = eluf(v.z * ssc[c + 2] + ssh[c + 2]);
                v.w = eluf(v.w * ssc[c + 3] + ssh[c + 3]);
            }
            uint4 w = make_uint4(f2tf(v.x), f2tf(v.y), f2tf(v.z), f2tf(v.w));
            *(uint4*)&sA[row * RA + c4] = w;
        }
#pragma unroll
        for (int i = 0; i < NBF; i++) {
            int f = i * 256 + t;
            int krow = f / (BN_ / 4);
            int c4 = (f % (BN_ / 4)) << 2;
            float4 v = *(const float4*)&B[(size_t)(k0 + krow) * NT + colBase + c4];
            uint4 w = make_uint4(f2tf(v.x), f2tf(v.y), f2tf(v.z), f2tf(v.w));
            *(uint4*)&sB[krow * RB + c4] = w;
        }
        __syncthreads();

#pragma unroll
        for (int s = 0; s < 4; s++) {
            unsigned af[4][4], bf[NU][2];
            int ak = s * 8 + mmak;
#pragma unroll
            for (int m = 0; m < 4; m++) {
                int r = wr * 64 + m * 16 + mmarow;
                const unsigned* p = &sA[r * RA + ak];
                af[m][0] = p[0];
                af[m][1] = p[8 * RA];
                af[m][2] = p[4];
                af[m][3] = p[8 * RA + 4];
            }
#pragma unroll
            for (int u = 0; u < NU; u++) {
                int c = wc * (BN_ / 4) + u * 8 + mmarow;
                const unsigned* p = &sB[ak * RB + c];
                bf[u][0] = p[0];
                bf[u][1] = p[4 * RB];
            }
#pragma unroll
            for (int m = 0; m < 4; m++)
#pragma unroll
                for (int u = 0; u < NU; u++) {
                    asm volatile(
                        "mma.sync.aligned.m16n8k8.row.col.f32.tf32.tf32.f32 "
                        "{%0,%1,%2,%3}, {%4,%5,%6,%7}, {%8,%9}, {%0,%1,%2,%3};"
                        : "+f"(acc[m][u][0]), "+f"(acc[m][u][1]),
                          "+f"(acc[m][u][2]), "+f"(acc[m][u][3])
                        : "r"(af[m][0]), "r"(af[m][1]), "r"(af[m][2]), "r"(af[m][3]),
                          "r"(bf[u][0]), "r"(bf[u][1]));
                }
        }
    }

#pragma unroll
    for (int m = 0; m < 4; m++) {
        int r0 = rowBase + wr * 64 + m * 16 + mmarow;
#pragma unroll
        for (int u = 0; u < NU; u++) {
            int c = colBase + wc * (BN_ / 4) + u * 8 + mmak * 2;
            if (r0 < M)
                *(float2*)&C[(size_t)r0 * NT + c] = make_float2(acc[m][u][0], acc[m][u][1]);
            if (r0 + 8 < M)
                *(float2*)&C[(size_t)(r0 + 8) * NT + c] = make_float2(acc[m][u][2], acc[m][u][3]);
        }
    }
}

// ---------------- per-node attention scores (fp32, vectorized) + BN zeroing ----------------
template <int HC, int H>
__global__ __launch_bounds__(256) void kscores(const float* __restrict__ h,
                                               const float* __restrict__ atts,
                                               const float* __restrict__ attd,
                                               float* __restrict__ as_,
                                               float* __restrict__ ad_, int N) {
    if (blockIdx.x == 0 && threadIdx.x < 256) {
        g_bnsum[threadIdx.x] = 0.f;
        g_bnsq[threadIdx.x] = 0.f;
    }
    int w = (blockIdx.x * blockDim.x + threadIdx.x) >> 5;
    int lane = threadIdx.x & 31;
    if (w >= N) return;
    float aS = 0.f, aD = 0.f;
    if (HC == 256) {
        // lane covers cols [lane*8, lane*8+7]; head = lane>>3 (C=64)
        const float4* hr = (const float4*)&h[(size_t)w * 256];
        float4 v0 = hr[lane * 2], v1 = hr[lane * 2 + 1];
        int c0 = lane * 8;
        float4 s0 = *(const float4*)&atts[c0], s1 = *(const float4*)&atts[c0 + 4];
        float4 t0 = *(const float4*)&attd[c0], t1 = *(const float4*)&attd[c0 + 4];
        aS = v0.x * s0.x + v0.y * s0.y + v0.z * s0.z + v0.w * s0.w
           + v1.x * s1.x + v1.y * s1.y + v1.z * s1.z + v1.w * s1.w;
        aD = v0.x * t0.x + v0.y * t0.y + v0.z * t0.z + v0.w * t0.w
           + v1.x * t1.x + v1.y * t1.y + v1.z * t1.z + v1.w * t1.w;
    } else if (HC == 128) {
        // lane covers cols [lane*4, lane*4+3]; head = lane>>3 (C=32)
        const float4* hr = (const float4*)&h[(size_t)w * 128];
        float4 v = hr[lane];
        int c0 = lane * 4;
        float4 s = *(const float4*)&atts[c0];
        float4 t0 = *(const float4*)&attd[c0];
        aS = v.x * s.x + v.y * s.y + v.z * s.z + v.w * s.w;
        aD = v.x * t0.x + v.y * t0.y + v.z * t0.z + v.w * t0.w;
    } else {
        const float2* hr = (const float2*)&h[(size_t)w * 64];
        float2 v = hr[lane];
        int c0 = lane * 2;
        aS = v.x * atts[c0] + v.y * atts[c0 + 1];
        aD = v.x * attd[c0] + v.y * attd[c0 + 1];
    }
    if (H == 4) {
#pragma unroll
        for (int o = 4; o > 0; o >>= 1) {
            aS += __shfl_xor_sync(0xffffffffu, aS, o);
            aD += __shfl_xor_sync(0xffffffffu, aD, o);
        }
        if ((lane & 7) == 0) {
            int hh = lane >> 3;
            as_[w * 4 + hh] = aS;
            ad_[w * 4 + hh] = aD;
        }
    } else {
#pragma unroll
        for (int o = 16; o > 0; o >>= 1) {
            aS += __shfl_xor_sync(0xffffffffu, aS, o);
            aD += __shfl_xor_sync(0xffffffffu, aD, o);
        }
        if (lane == 0) { as_[w] = aS; ad_[w] = aD; }
    }
}

// ---------------- fused segment-softmax + aggregation + atomic-free BN stats ----------------
// 8-edge software pipeline in pass B maximizes loads in flight.
template <int HC, int H>
__global__ __launch_bounds__(256, 2) void kmsg(
    const float* __restrict__ h, const float* __restrict__ as_,
    const float* __restrict__ ad_, const float* __restrict__ bias,
    float* __restrict__ out, int N)
{
    __shared__ float sS[8 * HC], sQ[8 * HC];
    int t = threadIdx.x;
    for (int i = t; i < 8 * HC; i += 256) { sS[i] = 0.f; sQ[i] = 0.f; }
    __syncthreads();

    int wid = t >> 5;
    int lane = t & 31;
    int w = blockIdx.x * 8 + wid;

    if (w < N) {
        int beg = g_off[w], end = g_off[w + 1];

        float ad0 = 0.f, ad1 = 0.f, ad2 = 0.f, ad3 = 0.f;
        if (H == 4) {
            float4 v = *(const float4*)&ad_[w * 4];
            ad0 = v.x; ad1 = v.y; ad2 = v.z; ad3 = v.w;
        } else {
            ad0 = ad_[w];
        }

        // ---- pass A: denominators ----
        float d0 = 0.f, d1 = 0.f, d2 = 0.f, d3 = 0.f;
        for (int e = beg + lane; e < end; e += 32) {
            int s = g_srcl[e];
            if (H == 4) {
                float4 a = *(const float4*)&as_[s * 4];
                d0 += __expf(lrelu2(a.x + ad0));
                d1 += __expf(lrelu2(a.y + ad1));
                d2 += __expf(lrelu2(a.z + ad2));
                d3 += __expf(lrelu2(a.w + ad3));
            } else {
                d0 += __expf(lrelu2(as_[s] + ad0));
            }
        }
#pragma unroll
        for (int o = 16; o > 0; o >>= 1) {
            d0 += __shfl_xor_sync(0xffffffffu, d0, o);
            if (H == 4) {
                d1 += __shfl_xor_sync(0xffffffffu, d1, o);
                d2 += __shfl_xor_sync(0xffffffffu, d2, o);
                d3 += __shfl_xor_sync(0xffffffffu, d3, o);
            }
        }
        float r0 = 1.0f / (d0 + 1e-16f);
        float r1 = 1.0f / (d1 + 1e-16f);
        float r2 = 1.0f / (d2 + 1e-16f);
        float r3 = 1.0f / (d3 + 1e-16f);

        // ---- pass B ----
        if (HC == 256) {
            int hA = (lane < 16) ? 0 : 1;
            float dA = (lane < 16) ? ad0 : ad1;
            float dB = (lane < 16) ? ad2 : ad3;
            float rA = (lane < 16) ? r0 : r1;
            float rB = (lane < 16) ? r2 : r3;
            const float4* h4 = (const float4*)h;
            float4 acc0 = make_float4(0.f, 0.f, 0.f, 0.f);
            float4 acc1 = make_float4(0.f, 0.f, 0.f, 0.f);
            int e = beg;
            for (; e + 8 <= end; e += 8) {
                int ss[8];
#pragma unroll
                for (int j = 0; j < 8; j++) ss[j] = g_srcl[e + j];
                float aA[8], aB[8];
#pragma unroll
                for (int j = 0; j < 8; j++) {
                    aA[j] = as_[ss[j] * 4 + hA];
                    aB[j] = as_[ss[j] * 4 + hA + 2];
                }
                float4 f0[8], f1[8];
#pragma unroll
                for (int j = 0; j < 8; j++) {
                    f0[j] = h4[(size_t)ss[j] * 64 + lane];
                    f1[j] = h4[(size_t)ss[j] * 64 + 32 + lane];
                }
#pragma unroll
                for (int j = 0; j < 8; j++) {
                    float lA = __expf(lrelu2(aA[j] + dA));
                    float lB = __expf(lrelu2(aB[j] + dB));
                    acc0.x += f0[j].x * lA; acc0.y += f0[j].y * lA;
                    acc0.z += f0[j].z * lA; acc0.w += f0[j].w * lA;
                    acc1.x += f1[j].x * lB; acc1.y += f1[j].y * lB;
                    acc1.z += f1[j].z * lB; acc1.w += f1[j].w * lB;
                }
            }
            for (; e < end; e++) {
                int s = g_srcl[e];
                float aA = as_[s * 4 + hA], aB = as_[s * 4 + hA + 2];
                float4 f0 = h4[(size_t)s * 64 + lane];
                float4 f1 = h4[(size_t)s * 64 + 32 + lane];
                float lA = __expf(lrelu2(aA + dA)), lB = __expf(lrelu2(aB + dB));
                acc0.x += f0.x * lA; acc0.y += f0.y * lA; acc0.z += f0.z * lA; acc0.w += f0.w * lA;
                acc1.x += f1.x * lB; acc1.y += f1.y * lB; acc1.z += f1.z * lB; acc1.w += f1.w * lB;
            }
            int c0 = lane * 4;
            float4 b0 = *(const float4*)&bias[c0];
            float4 b1 = *(const float4*)&bias[128 + c0];
            float4 v0 = make_float4(acc0.x * rA + b0.x, acc0.y * rA + b0.y,
                                    acc0.z * rA + b0.z, acc0.w * rA + b0.w);
            float4 v1 = make_float4(acc1.x * rB + b1.x, acc1.y * rB + b1.y,
                                    acc1.z * rB + b1.z, acc1.w * rB + b1.w);
            float* orow = &out[(size_t)w * 256];
            *(float4*)&orow[c0] = v0;
            *(float4*)&orow[128 + c0] = v1;
            *(float4*)&sS[wid * 256 + c0] = v0;
            *(float4*)&sS[wid * 256 + 128 + c0] = v1;
            *(float4*)&sQ[wid * 256 + c0] =
                make_float4(v0.x * v0.x, v0.y * v0.y, v0.z * v0.z, v0.w * v0.w);
            *(float4*)&sQ[wid * 256 + 128 + c0] =
                make_float4(v1.x * v1.x, v1.y * v1.y, v1.z * v1.z, v1.w * v1.w);
        } else if (HC == 128) {
            int hs = lane >> 3;
            float dh = hs == 0 ? ad0 : hs == 1 ? ad1 : hs == 2 ? ad2 : ad3;
            float rh = hs == 0 ? r0 : hs == 1 ? r1 : hs == 2 ? r2 : r3;
            const float4* h4 = (const float4*)h;
            float4 acc = make_float4(0.f, 0.f, 0.f, 0.f);
            int e = beg;
            for (; e + 8 <= end; e += 8) {
                int ss[8];
#pragma unroll
                for (int j = 0; j < 8; j++) ss[j] = g_srcl[e + j];
                float a[8];
#pragma unroll
                for (int j = 0; j < 8; j++) a[j] = as_[ss[j] * 4 + hs];
                float4 f[8];
#pragma unroll
                for (int j = 0; j < 8; j++) f[j] = h4[(size_t)ss[j] * 32 + lane];
#pragma unroll
                for (int j = 0; j < 8; j++) {
                    float l = __expf(lrelu2(a[j] + dh));
                    acc.x += f[j].x * l; acc.y += f[j].y * l;
                    acc.z += f[j].z * l; acc.w += f[j].w * l;
                }
            }
            for (; e < end; e++) {
                int s = g_srcl[e];
                float a = as_[s * 4 + hs];
                float4 f = h4[(size_t)s * 32 + lane];
                float l = __expf(lrelu2(a + dh));
                acc.x += f.x * l; acc.y += f.y * l; acc.z += f.z * l; acc.w += f.w * l;
            }
            int c0 = lane * 4;
            float4 b = *(const float4*)&bias[c0];
            float4 v = make_float4(acc.x * rh + b.x, acc.y * rh + b.y,
                                   acc.z * rh + b.z, acc.w * rh + b.w);
            *(float4*)&out[(size_t)w * 128 + c0] = v;
            *(float4*)&sS[wid * 128 + c0] = v;
            *(float4*)&sQ[wid * 128 + c0] =
                make_float4(v.x * v.x, v.y * v.y, v.z * v.z, v.w * v.w);
        } else { // HC == 64, H == 1
            const float2* h2 = (const float2*)h;
            float ax = 0.f, ay = 0.f;
            int e = beg;
            for (; e + 8 <= end; e += 8) {
                int ss[8];
#pragma unroll
                for (int j = 0; j < 8; j++) ss[j] = g_srcl[e + j];
                float a[8];
#pragma unroll
                for (int j = 0; j < 8; j++) a[j] = as_[ss[j]];
                float2 f[8];
#pragma unroll
                for (int j = 0; j < 8; j++) f[j] = h2[(size_t)ss[j] * 32 + lane];
#pragma unroll
                for (int j = 0; j < 8; j++) {
                    float l = __expf(lrelu2(a[j] + ad0));
                    ax += f[j].x * l; ay += f[j].y * l;
                }
            }
            for (; e < end; e++) {
                int s = g_srcl[e];
                float a = as_[s];
                float2 f = h2[(size_t)s * 32 + lane];
                float l = __expf(lrelu2(a + ad0));
                ax += f.x * l; ay += f.y * l;
            }
            int c0 = lane * 2;
            float v0 = ax * r0 + bias[c0];
            float v1 = ay * r0 + bias[c0 + 1];
            *(float2*)&out[(size_t)w * 64 + c0] = make_float2(v0, v1);
            *(float2*)&sS[wid * 64 + c0] = make_float2(v0, v1);
            *(float2*)&sQ[wid * 64 + c0] = make_float2(v0 * v0, v1 * v1);
        }
    }
    __syncthreads();
    if (t < HC) {
        float s = 0.f, q = 0.f;
#pragma unroll
        for (int wpb = 0; wpb < 8; wpb++) {
            s += sS[wpb * HC + t];
            q += sQ[wpb * HC + t];
        }
        atomicAdd(&g_bnsum[t], s);
        atomicAdd(&g_bnsq[t], q);
    }
}

// ---------------- global mean pool (BN+ELU inline) + MLP ----------------
__global__ void kpool(const float* __restrict__ hfin, const int* __restrict__ batch,
                      const float* __restrict__ gam, const float* __restrict__ bet, int N) {
    __shared__ float ssc[64], ssh[64];
    if (threadIdx.x < 64) {
        int f = threadIdx.x;
        float invN = 1.0f / (float)N;
        float mean = g_bnsum[f] * invN;
        float var = g_bnsq[f] * invN - mean * mean;
        float s = rsqrtf(var + 1e-5f) * gam[f];
        ssc[f] = s;
        ssh[f] = bet[f] - mean * s;
    }
    __syncthreads();
    int i = blockIdx.x * blockDim.x + threadIdx.x;
    if (i >= N * 64) return;
    int n = i >> 6, f = i & 63;
    float v = hfin[i] * ssc[f] + ssh[f];
    v = v > 0.f ? v : (__expf(v) - 1.0f);
    int gph = batch[n];
    atomicAdd(&g_pool[gph * 64 + f], v);
    if (f == 0) atomicAdd(&g_cnt[gph], 1.0f);
}

__global__ __launch_bounds__(128) void kmlp(const float* __restrict__ fw1, const float* __restrict__ fb1,
                                            const float* __restrict__ fw2, const float* __restrict__ fb2,
                                            const float* __restrict__ fw3, const float* __restrict__ fb3,
                                            float* __restrict__ out) {
    __shared__ float sp[64 * 64];
    __shared__ float sz1[64 * 128];
    __shared__ float sz2[64 * 32];
    int t = threadIdx.x;
    for (int i = t; i < 64 * 64; i += 128) {
        int gph = i >> 6;
        float c = g_cnt[gph];
        sp[i] = g_pool[i] / fmaxf(c, 1.0f);
    }
    __syncthreads();
    for (int i = t; i < 64 * 128; i += 128) {
        int gph = i >> 7, j = i & 127;
        float a = fb1[j];
        for (int f = 0; f < 64; f++) a += sp[gph * 64 + f] * fw1[f * 128 + j];
        sz1[i] = lrelu2(a);
    }
    __syncthreads();
    for (int i = t; i < 64 * 32; i += 128) {
        int gph = i >> 5, j = i & 31;
        float a = fb2[j];
        for (int f = 0; f < 128; f++) a += sz1[gph * 128 + f] * fw2[f * 32 + j];
        sz2[i] = lrelu2(a);
    }
    __syncthreads();
    for (int i = t; i < 64 * 2; i += 128) {
        int gph = i >> 1, j = i & 1;
        float a = fb3[j];
        for (int f = 0; f < 32; f++) a += sz2[gph * 32 + f] * fw3[f * 2 + j];
        out[i] = a;
    }
}

// ---------------- host launcher ----------------
extern "C" void kernel_launch(void* const* d_in, const int* in_sizes, int n_in,
                              void* d_out, int out_size) {
    const float* x     = (const float*)d_in[0];
    const int*   ei    = (const int*)d_in[1];
    const int*   batch = (const int*)d_in[2];
    const float* W1  = (const float*)d_in[3];
    const float* as1 = (const float*)d_in[4];
    const float* ad1 = (const float*)d_in[5];
    const float* b1  = (const float*)d_in[6];
    const float* W2  = (const float*)d_in[7];
    const float* as2 = (const float*)d_in[8];
    const float* ad2 = (const float*)d_in[9];
    const float* b2  = (const float*)d_in[10];
    const float* W3  = (const float*)d_in[11];
    const float* as3 = (const float*)d_in[12];
    const float* ad3 = (const float*)d_in[13];
    const float* b3  = (const float*)d_in[14];
    const float* g1  = (const float*)d_in[15];
    const float* bt1 = (const float*)d_in[16];
    const float* g2  = (const float*)d_in[17];
    const float* bt2 = (const float*)d_in[18];
    const float* g3  = (const float*)d_in[19];
    const float* bt3 = (const float*)d_in[20];
    const float* fw1 = (const float*)d_in[21];
    const float* fb1 = (const float*)d_in[22];
    const float* fw2 = (const float*)d_in[23];
    const float* fb2 = (const float*)d_in[24];
    const float* fw3 = (const float*)d_in[25];
    const float* fb3 = (const float*)d_in[26];

    int N = in_sizes[0] / 128;
    int E = in_sizes[1] / 2;
    int ET = E + N;

    float *ph, *po, *pas, *pad;
    cudaGetSymbolAddress((void**)&ph,  g_h);
    cudaGetSymbolAddress((void**)&po,  g_o);
    cudaGetSymbolAddress((void**)&pas, g_as);
    cudaGetSymbolAddress((void**)&pad, g_ad);

    int wblocks = (N * 32 + 255) / 256;
    int nblocks = (N + 7) / 8;
    int mblocks = (N + 127) / 128;

    kzero_deg<<<(N + 255) / 256, 256>>>(N);
    khist<<<(ET + 255) / 256, 256>>>(ei, E, N);
    kscan<<<1, 1024>>>(N);
    tgemm<128, false><<<dim3(2, mblocks), 256>>>(x, W1, ph, N, 256, 128, nullptr, nullptr);
    kscatter<<<(ET + 255) / 256, 256>>>(ei, E, N);

    // ---- layer 1: 128 -> 4x64 ----
    kscores<256, 4><<<wblocks, 256>>>(ph, as1, ad1, pas, pad, N);
    kmsg<256, 4><<<nblocks, 256>>>(ph, pas, pad, b1, po, N);

    // ---- layer 2: 256 -> 4x32 (BN+ELU fused into A-load) ----
    tgemm<128, true><<<dim3(1, mblocks), 256>>>(po, W2, ph, N, 128, 256, g1, bt1);
    kscores<128, 4><<<wblocks, 256>>>(ph, as2, ad2, pas, pad, N);
    kmsg<128, 4><<<nblocks, 256>>>(ph, pas, pad, b2, po, N);

    // ---- layer 3: 128 -> 1x64 (BN+ELU fused into A-load) ----
    tgemm<64, true><<<dim3(1, mblocks), 256>>>(po, W3, ph, N, 64, 128, g2, bt2);
    kscores<64, 1><<<wblocks, 256>>>(ph, as3, ad3, pas, pad, N);
    kmsg<64, 1><<<nblocks, 256>>>(ph, pas, pad, b3, po, N);

    // ---- pool (BN+ELU inline) + MLP ----
    kpool<<<(N * 64 + 255) / 256, 256>>>(po, batch, g3, bt3, N);
    kmlp<<<1, 128>>>(fw1, fb1, fw2, fb2, fw3, fb3, (float*)d_out);
}

// round 9
// speedup vs baseline: 1.0526x; 1.0526x over previous
#include <cuda_runtime.h>
#include <math.h>
#include <stdint.h>

// ---------------- static scratch (no allocations allowed) ----------------
#define MAXN 50000
#define MAXE 800000
#define MAXT (MAXN + MAXE)

__device__ int   g_deg[MAXN];
__device__ int   g_off[MAXN + 1];
__device__ int   g_cur[MAXN];
__device__ int   g_srcl[MAXT];
__device__ __align__(16) float g_h[(size_t)MAXN * 256];
__device__ __align__(16) float g_o[(size_t)MAXN * 256];
__device__ __align__(16) float g_as[MAXN * 4];
__device__ __align__(16) float g_ad[MAXN * 4];
__device__ float g_bnsum[256];
__device__ float g_bnsq[256];
__device__ float g_pool[64 * 64];
__device__ float g_cnt[64];

__device__ __forceinline__ float lrelu2(float v) { return v > 0.f ? v : 0.2f * v; }
__device__ __forceinline__ float eluf(float v) { return v > 0.f ? v : (__expf(v) - 1.0f); }
__device__ __forceinline__ unsigned f2tf(float x) {
    unsigned r;
    asm("cvt.rna.tf32.f32 %0, %1;" : "=r"(r) : "f"(x));
    return r;
}

// ---------------- CSR build ----------------
__global__ void kzero_deg(int N) {
    int i = blockIdx.x * blockDim.x + threadIdx.x;
    if (i < N) g_deg[i] = 0;
    if (i < 64 * 64) g_pool[i] = 0.f;
    if (i < 64) g_cnt[i] = 0.f;
}

__global__ void khist(const int* __restrict__ ei, int E, int N) {
    int i = blockIdx.x * blockDim.x + threadIdx.x;
    int T = E + N;
    if (i >= T) return;
    int d = (i < E) ? ei[E + i] : (i - E);
    atomicAdd(&g_deg[d], 1);
}

__global__ void kscan(int N) {
    __shared__ int sh[1024];
    int t = threadIdx.x;
    int chunk = (N + 1023) >> 10;
    int b = t * chunk;
    int e = min(b + chunk, N);
    int s = 0;
    for (int i = b; i < e; i++) s += g_deg[i];
    sh[t] = s;
    __syncthreads();
    for (int off = 1; off < 1024; off <<= 1) {
        int v = (t >= off) ? sh[t - off] : 0;
        __syncthreads();
        sh[t] += v;
        __syncthreads();
    }
    int run = (t == 0) ? 0 : sh[t - 1];
    for (int i = b; i < e; i++) {
        g_off[i] = run;
        g_cur[i] = run;
        run += g_deg[i];
    }
    if (t == 1023) g_off[N] = sh[1023];
}

__global__ void kscatter(const int* __restrict__ ei, int E, int N) {
    int i = blockIdx.x * blockDim.x + threadIdx.x;
    int T = E + N;
    if (i >= T) return;
    int s, d;
    if (i < E) { s = ei[i]; d = ei[E + i]; }
    else       { s = i - E; d = i - E; }
    int pos = atomicAdd(&g_cur[d], 1);
    g_srcl[pos] = s;
}

// ---------------- TF32 tensor-core GEMM: C[M,NT] = A[M,K] @ B[K,NT] (fp32 out) ----------------
template <int BN_, bool FUSE>
__global__ __launch_bounds__(256, 2) void tgemm(
    const float* __restrict__ A, const float* __restrict__ B, float* __restrict__ C,
    int M, int NT, int K,
    const float* __restrict__ gam, const float* __restrict__ bet)
{
    constexpr int BM_ = 128, BK_ = 32;
    constexpr int RA = BK_ + 4;
    constexpr int RB = BN_ + 8;
    constexpr int NU = BN_ / 32;
    constexpr int NBF = BK_ * BN_ / 4 / 256;

    __shared__ unsigned sA[BM_ * RA];
    __shared__ unsigned sB[BK_ * RB];
    __shared__ float ssc[256], ssh[256];

    const int t = threadIdx.x;
    const int lane = t & 31;
    const int wid = t >> 5;
    const int wr = wid >> 2;
    const int wc = wid & 3;
    const int rowBase = blockIdx.y * BM_;
    const int colBase = blockIdx.x * BN_;
    const int mmarow = lane >> 2;
    const int mmak = lane & 3;

    if (FUSE) {
        float invN = 1.0f / (float)M;
        for (int i = t; i < K; i += 256) {
            float mean = g_bnsum[i] * invN;
            float var = g_bnsq[i] * invN - mean * mean;
            float s = rsqrtf(var + 1e-5f) * gam[i];
            ssc[i] = s;
            ssh[i] = bet[i] - mean * s;
        }
    }

    float acc[4][NU][4];
#pragma unroll
    for (int m = 0; m < 4; m++)
#pragma unroll
        for (int u = 0; u < NU; u++)
#pragma unroll
            for (int j = 0; j < 4; j++) acc[m][u][j] = 0.f;

    for (int k0 = 0; k0 < K; k0 += BK_) {
        __syncthreads();
#pragma unroll
        for (int i = 0; i < 4; i++) {
            int f = i * 256 + t;
            int row = f >> 3;
            int c4 = (f & 7) << 2;
            int gr = rowBase + row;
            float4 v = make_float4(0.f, 0.f, 0.f, 0.f);
            if (gr < M) v = *(const float4*)&A[(size_t)gr * K + k0 + c4];
            if (FUSE) {
                int c = k0 + c4;
                v.x = eluf(v.x * ssc[c + 0] + ssh[c + 0]);
                v.y = eluf(v.y * ssc[c + 1] + ssh[c + 1]);
                v.z = eluf(v.z * ssc[c + 2] + ssh[c + 2]);
                v.w = eluf(v.w * ssc[c + 3] + ssh[c + 3]);
            }
            uint4 w = make_uint4(f2tf(v.x), f2tf(v.y), f2tf(v.z), f2tf(v.w));
            *(uint4*)&sA[row * RA + c4] = w;
        }
#pragma unroll
        for (int i = 0; i < NBF; i++) {
            int f = i * 256 + t;
            int krow = f / (BN_ / 4);
            int c4 = (f % (BN_ / 4)) << 2;
            float4 v = *(const float4*)&B[(size_t)(k0 + krow) * NT + colBase + c4];
            uint4 w = make_uint4(f2tf(v.x), f2tf(v.y), f2tf(v.z), f2tf(v.w));
            *(uint4*)&sB[krow * RB + c4] = w;
        }
        __syncthreads();

#pragma unroll
        for (int s = 0; s < 4; s++) {
            unsigned af[4][4], bf[NU][2];
            int ak = s * 8 + mmak;
#pragma unroll
            for (int m = 0; m < 4; m++) {
                int r = wr * 64 + m * 16 + mmarow;
                const unsigned* p = &sA[r * RA + ak];
                af[m][0] = p[0];
                af[m][1] = p[8 * RA];
                af[m][2] = p[4];
                af[m][3] = p[8 * RA + 4];
            }
#pragma unroll
            for (int u = 0; u < NU; u++) {
                int c = wc * (BN_ / 4) + u * 8 + mmarow;
                const unsigned* p = &sB[ak * RB + c];
                bf[u][0] = p[0];
                bf[u][1] = p[4 * RB];
            }
#pragma unroll
            for (int m = 0; m < 4; m++)
#pragma unroll
                for (int u = 0; u < NU; u++) {
                    asm volatile(
                        "mma.sync.aligned.m16n8k8.row.col.f32.tf32.tf32.f32 "
                        "{%0,%1,%2,%3}, {%4,%5,%6,%7}, {%8,%9}, {%0,%1,%2,%3};"
                        : "+f"(acc[m][u][0]), "+f"(acc[m][u][1]),
                          "+f"(acc[m][u][2]), "+f"(acc[m][u][3])
                        : "r"(af[m][0]), "r"(af[m][1]), "r"(af[m][2]), "r"(af[m][3]),
                          "r"(bf[u][0]), "r"(bf[u][1]));
                }
        }
    }

#pragma unroll
    for (int m = 0; m < 4; m++) {
        int r0 = rowBase + wr * 64 + m * 16 + mmarow;
#pragma unroll
        for (int u = 0; u < NU; u++) {
            int c = colBase + wc * (BN_ / 4) + u * 8 + mmak * 2;
            if (r0 < M)
                *(float2*)&C[(size_t)r0 * NT + c] = make_float2(acc[m][u][0], acc[m][u][1]);
            if (r0 + 8 < M)
                *(float2*)&C[(size_t)(r0 + 8) * NT + c] = make_float2(acc[m][u][2], acc[m][u][3]);
        }
    }
}

// ---------------- per-node attention scores (fp32, vectorized) + BN zeroing ----------------
template <int HC, int H>
__global__ __launch_bounds__(256) void kscores(const float* __restrict__ h,
                                               const float* __restrict__ atts,
                                               const float* __restrict__ attd,
                                               float* __restrict__ as_,
                                               float* __restrict__ ad_, int N) {
    if (blockIdx.x == 0 && threadIdx.x < 256) {
        g_bnsum[threadIdx.x] = 0.f;
        g_bnsq[threadIdx.x] = 0.f;
    }
    int w = (blockIdx.x * blockDim.x + threadIdx.x) >> 5;
    int lane = threadIdx.x & 31;
    if (w >= N) return;
    float aS = 0.f, aD = 0.f;
    if (HC == 256) {
        const float4* hr = (const float4*)&h[(size_t)w * 256];
        float4 v0 = hr[lane * 2], v1 = hr[lane * 2 + 1];
        int c0 = lane * 8;
        float4 s0 = *(const float4*)&atts[c0], s1 = *(const float4*)&atts[c0 + 4];
        float4 t0 = *(const float4*)&attd[c0], t1 = *(const float4*)&attd[c0 + 4];
        aS = v0.x * s0.x + v0.y * s0.y + v0.z * s0.z + v0.w * s0.w
           + v1.x * s1.x + v1.y * s1.y + v1.z * s1.z + v1.w * s1.w;
        aD = v0.x * t0.x + v0.y * t0.y + v0.z * t0.z + v0.w * t0.w
           + v1.x * t1.x + v1.y * t1.y + v1.z * t1.z + v1.w * t1.w;
    } else if (HC == 128) {
        const float4* hr = (const float4*)&h[(size_t)w * 128];
        float4 v = hr[lane];
        int c0 = lane * 4;
        float4 s = *(const float4*)&atts[c0];
        float4 t0 = *(const float4*)&attd[c0];
        aS = v.x * s.x + v.y * s.y + v.z * s.z + v.w * s.w;
        aD = v.x * t0.x + v.y * t0.y + v.z * t0.z + v.w * t0.w;
    } else {
        const float2* hr = (const float2*)&h[(size_t)w * 64];
        float2 v = hr[lane];
        int c0 = lane * 2;
        aS = v.x * atts[c0] + v.y * atts[c0 + 1];
        aD = v.x * attd[c0] + v.y * attd[c0 + 1];
    }
    if (H == 4) {
#pragma unroll
        for (int o = 4; o > 0; o >>= 1) {
            aS += __shfl_xor_sync(0xffffffffu, aS, o);
            aD += __shfl_xor_sync(0xffffffffu, aD, o);
        }
        if ((lane & 7) == 0) {
            int hh = lane >> 3;
            as_[w * 4 + hh] = aS;
            ad_[w * 4 + hh] = aD;
        }
    } else {
#pragma unroll
        for (int o = 16; o > 0; o >>= 1) {
            aS += __shfl_xor_sync(0xffffffffu, aS, o);
            aD += __shfl_xor_sync(0xffffffffu, aD, o);
        }
        if (lane == 0) { as_[w] = aS; ad_[w] = aD; }
    }
}

// ---------------- SINGLE-PASS segment-softmax + aggregation + atomic-free BN stats ----------------
// out = (Σ_e exp(lrelu(score_e)) * h[src_e]) / (Σ_e exp(lrelu(score_e)))
// Denominator accumulated redundantly per lane (every lane walks every edge) — no
// second pass, no warp reduction, division at the end. Mathematically identical.
template <int HC, int H>
__global__ __launch_bounds__(256, 2) void kmsg(
    const float* __restrict__ h, const float* __restrict__ as_,
    const float* __restrict__ ad_, const float* __restrict__ bias,
    float* __restrict__ out, int N)
{
    __shared__ float sS[8 * HC], sQ[8 * HC];
    int t = threadIdx.x;
    for (int i = t; i < 8 * HC; i += 256) { sS[i] = 0.f; sQ[i] = 0.f; }
    __syncthreads();

    int wid = t >> 5;
    int lane = t & 31;
    int w = blockIdx.x * 8 + wid;

    if (w < N) {
        int beg = g_off[w], end = g_off[w + 1];

        float ad0 = 0.f, ad1 = 0.f, ad2 = 0.f, ad3 = 0.f;
        if (H == 4) {
            float4 v = *(const float4*)&ad_[w * 4];
            ad0 = v.x; ad1 = v.y; ad2 = v.z; ad3 = v.w;
        } else {
            ad0 = ad_[w];
        }

        if (HC == 256) {
            // lane handles cols [lane*4..+3] (head A = lane<16 ? 0 : 1) and
            // cols [128+lane*4..+3] (head B = A+2).
            int hA = (lane < 16) ? 0 : 1;
            float dA = (lane < 16) ? ad0 : ad1;
            float dB = (lane < 16) ? ad2 : ad3;
            const float4* h4 = (const float4*)h;
            float4 acc0 = make_float4(0.f, 0.f, 0.f, 0.f);
            float4 acc1 = make_float4(0.f, 0.f, 0.f, 0.f);
            float denA = 0.f, denB = 0.f;
            int e = beg;
            for (; e + 4 <= end; e += 4) {
                int s0 = g_srcl[e], s1 = g_srcl[e + 1], s2 = g_srcl[e + 2], s3 = g_srcl[e + 3];
                float aA0 = as_[s0 * 4 + hA], aB0 = as_[s0 * 4 + hA + 2];
                float aA1 = as_[s1 * 4 + hA], aB1 = as_[s1 * 4 + hA + 2];
                float aA2 = as_[s2 * 4 + hA], aB2 = as_[s2 * 4 + hA + 2];
                float aA3 = as_[s3 * 4 + hA], aB3 = as_[s3 * 4 + hA + 2];
                float4 f00 = h4[(size_t)s0 * 64 + lane];
                float4 f01 = h4[(size_t)s0 * 64 + 32 + lane];
                float4 f10 = h4[(size_t)s1 * 64 + lane];
                float4 f11 = h4[(size_t)s1 * 64 + 32 + lane];
                float4 f20 = h4[(size_t)s2 * 64 + lane];
                float4 f21 = h4[(size_t)s2 * 64 + 32 + lane];
                float4 f30 = h4[(size_t)s3 * 64 + lane];
                float4 f31 = h4[(size_t)s3 * 64 + 32 + lane];
                float lA0 = __expf(lrelu2(aA0 + dA)), lB0 = __expf(lrelu2(aB0 + dB));
                float lA1 = __expf(lrelu2(aA1 + dA)), lB1 = __expf(lrelu2(aB1 + dB));
                float lA2 = __expf(lrelu2(aA2 + dA)), lB2 = __expf(lrelu2(aB2 + dB));
                float lA3 = __expf(lrelu2(aA3 + dA)), lB3 = __expf(lrelu2(aB3 + dB));
                denA += lA0 + lA1 + lA2 + lA3;
                denB += lB0 + lB1 + lB2 + lB3;
                acc0.x += f00.x * lA0; acc0.y += f00.y * lA0; acc0.z += f00.z * lA0; acc0.w += f00.w * lA0;
                acc1.x += f01.x * lB0; acc1.y += f01.y * lB0; acc1.z += f01.z * lB0; acc1.w += f01.w * lB0;
                acc0.x += f10.x * lA1; acc0.y += f10.y * lA1; acc0.z += f10.z * lA1; acc0.w += f10.w * lA1;
                acc1.x += f11.x * lB1; acc1.y += f11.y * lB1; acc1.z += f11.z * lB1; acc1.w += f11.w * lB1;
                acc0.x += f20.x * lA2; acc0.y += f20.y * lA2; acc0.z += f20.z * lA2; acc0.w += f20.w * lA2;
                acc1.x += f21.x * lB2; acc1.y += f21.y * lB2; acc1.z += f21.z * lB2; acc1.w += f21.w * lB2;
                acc0.x += f30.x * lA3; acc0.y += f30.y * lA3; acc0.z += f30.z * lA3; acc0.w += f30.w * lA3;
                acc1.x += f31.x * lB3; acc1.y += f31.y * lB3; acc1.z += f31.z * lB3; acc1.w += f31.w * lB3;
            }
            for (; e < end; e++) {
                int s = g_srcl[e];
                float aA = as_[s * 4 + hA], aB = as_[s * 4 + hA + 2];
                float4 f0 = h4[(size_t)s * 64 + lane];
                float4 f1 = h4[(size_t)s * 64 + 32 + lane];
                float lA = __expf(lrelu2(aA + dA)), lB = __expf(lrelu2(aB + dB));
                denA += lA; denB += lB;
                acc0.x += f0.x * lA; acc0.y += f0.y * lA; acc0.z += f0.z * lA; acc0.w += f0.w * lA;
                acc1.x += f1.x * lB; acc1.y += f1.y * lB; acc1.z += f1.z * lB; acc1.w += f1.w * lB;
            }
            float rA = 1.0f / (denA + 1e-16f);
            float rB = 1.0f / (denB + 1e-16f);
            int c0 = lane * 4;
            float4 b0 = *(const float4*)&bias[c0];
            float4 b1 = *(const float4*)&bias[128 + c0];
            float4 v0 = make_float4(acc0.x * rA + b0.x, acc0.y * rA + b0.y,
                                    acc0.z * rA + b0.z, acc0.w * rA + b0.w);
            float4 v1 = make_float4(acc1.x * rB + b1.x, acc1.y * rB + b1.y,
                                    acc1.z * rB + b1.z, acc1.w * rB + b1.w);
            float* orow = &out[(size_t)w * 256];
            *(float4*)&orow[c0] = v0;
            *(float4*)&orow[128 + c0] = v1;
            *(float4*)&sS[wid * 256 + c0] = v0;
            *(float4*)&sS[wid * 256 + 128 + c0] = v1;
            *(float4*)&sQ[wid * 256 + c0] =
                make_float4(v0.x * v0.x, v0.y * v0.y, v0.z * v0.z, v0.w * v0.w);
            *(float4*)&sQ[wid * 256 + 128 + c0] =
                make_float4(v1.x * v1.x, v1.y * v1.y, v1.z * v1.z, v1.w * v1.w);
        } else if (HC == 128) {
            int hs = lane >> 3;
            float dh = hs == 0 ? ad0 : hs == 1 ? ad1 : hs == 2 ? ad2 : ad3;
            const float4* h4 = (const float4*)h;
            float4 acc = make_float4(0.f, 0.f, 0.f, 0.f);
            float den = 0.f;
            int e = beg;
            for (; e + 4 <= end; e += 4) {
                int s0 = g_srcl[e], s1 = g_srcl[e + 1], s2 = g_srcl[e + 2], s3 = g_srcl[e + 3];
                float a0 = as_[s0 * 4 + hs];
                float a1 = as_[s1 * 4 + hs];
                float a2 = as_[s2 * 4 + hs];
                float a3 = as_[s3 * 4 + hs];
                float4 f0 = h4[(size_t)s0 * 32 + lane];
                float4 f1 = h4[(size_t)s1 * 32 + lane];
                float4 f2 = h4[(size_t)s2 * 32 + lane];
                float4 f3 = h4[(size_t)s3 * 32 + lane];
                float l0 = __expf(lrelu2(a0 + dh));
                float l1 = __expf(lrelu2(a1 + dh));
                float l2 = __expf(lrelu2(a2 + dh));
                float l3 = __expf(lrelu2(a3 + dh));
                den += l0 + l1 + l2 + l3;
                acc.x += f0.x * l0; acc.y += f0.y * l0; acc.z += f0.z * l0; acc.w += f0.w * l0;
                acc.x += f1.x * l1; acc.y += f1.y * l1; acc.z += f1.z * l1; acc.w += f1.w * l1;
                acc.x += f2.x * l2; acc.y += f2.y * l2; acc.z += f2.z * l2; acc.w += f2.w * l2;
                acc.x += f3.x * l3; acc.y += f3.y * l3; acc.z += f3.z * l3; acc.w += f3.w * l3;
            }
            for (; e < end; e++) {
                int s = g_srcl[e];
                float a = as_[s * 4 + hs];
                float4 f = h4[(size_t)s * 32 + lane];
                float l = __expf(lrelu2(a + dh));
                den += l;
                acc.x += f.x * l; acc.y += f.y * l; acc.z += f.z * l; acc.w += f.w * l;
            }
            float rh = 1.0f / (den + 1e-16f);
            int c0 = lane * 4;
            float4 b = *(const float4*)&bias[c0];
            float4 v = make_float4(acc.x * rh + b.x, acc.y * rh + b.y,
                                   acc.z * rh + b.z, acc.w * rh + b.w);
            *(float4*)&out[(size_t)w * 128 + c0] = v;
            *(float4*)&sS[wid * 128 + c0] = v;
            *(float4*)&sQ[wid * 128 + c0] =
                make_float4(v.x * v.x, v.y * v.y, v.z * v.z, v.w * v.w);
        } else { // HC == 64, H == 1
            const float2* h2 = (const float2*)h;
            float ax = 0.f, ay = 0.f, den = 0.f;
            int e = beg;
            for (; e + 4 <= end; e += 4) {
                int s0 = g_srcl[e], s1 = g_srcl[e + 1], s2 = g_srcl[e + 2], s3 = g_srcl[e + 3];
                float a0 = as_[s0], a1 = as_[s1], a2 = as_[s2], a3 = as_[s3];
                float2 f0 = h2[(size_t)s0 * 32 + lane];
                float2 f1 = h2[(size_t)s1 * 32 + lane];
                float2 f2 = h2[(size_t)s2 * 32 + lane];
                float2 f3 = h2[(size_t)s3 * 32 + lane];
                float l0 = __expf(lrelu2(a0 + ad0));
                float l1 = __expf(lrelu2(a1 + ad0));
                float l2 = __expf(lrelu2(a2 + ad0));
                float l3 = __expf(lrelu2(a3 + ad0));
                den += l0 + l1 + l2 + l3;
                ax += f0.x * l0; ay += f0.y * l0;
                ax += f1.x * l1; ay += f1.y * l1;
                ax += f2.x * l2; ay += f2.y * l2;
                ax += f3.x * l3; ay += f3.y * l3;
            }
            for (; e < end; e++) {
                int s = g_srcl[e];
                float a = as_[s];
                float2 f = h2[(size_t)s * 32 + lane];
                float l = __expf(lrelu2(a + ad0));
                den += l;
                ax += f.x * l; ay += f.y * l;
            }
            float r0 = 1.0f / (den + 1e-16f);
            int c0 = lane * 2;
            float v0 = ax * r0 + bias[c0];
            float v1 = ay * r0 + bias[c0 + 1];
            *(float2*)&out[(size_t)w * 64 + c0] = make_float2(v0, v1);
            *(float2*)&sS[wid * 64 + c0] = make_float2(v0, v1);
            *(float2*)&sQ[wid * 64 + c0] = make_float2(v0 * v0, v1 * v1);
        }
    }
    __syncthreads();
    if (t < HC) {
        float s = 0.f, q = 0.f;
#pragma unroll
        for (int wpb = 0; wpb < 8; wpb++) {
            s += sS[wpb * HC + t];
            q += sQ[wpb * HC + t];
        }
        atomicAdd(&g_bnsum[t], s);
        atomicAdd(&g_bnsq[t], q);
    }
}

// ---------------- global mean pool (BN+ELU inline) + MLP ----------------
__global__ void kpool(const float* __restrict__ hfin, const int* __restrict__ batch,
                      const float* __restrict__ gam, const float* __restrict__ bet, int N) {
    __shared__ float ssc[64], ssh[64];
    if (threadIdx.x < 64) {
        int f = threadIdx.x;
        float invN = 1.0f / (float)N;
        float mean = g_bnsum[f] * invN;
        float var = g_bnsq[f] * invN - mean * mean;
        float s = rsqrtf(var + 1e-5f) * gam[f];
        ssc[f] = s;
        ssh[f] = bet[f] - mean * s;
    }
    __syncthreads();
    int i = blockIdx.x * blockDim.x + threadIdx.x;
    if (i >= N * 64) return;
    int n = i >> 6, f = i & 63;
    float v = hfin[i] * ssc[f] + ssh[f];
    v = v > 0.f ? v : (__expf(v) - 1.0f);
    int gph = batch[n];
    atomicAdd(&g_pool[gph * 64 + f], v);
    if (f == 0) atomicAdd(&g_cnt[gph], 1.0f);
}

__global__ __launch_bounds__(128) void kmlp(const float* __restrict__ fw1, const float* __restrict__ fb1,
                                            const float* __restrict__ fw2, const float* __restrict__ fb2,
                                            const float* __restrict__ fw3, const float* __restrict__ fb3,
                                            float* __restrict__ out) {
    __shared__ float sp[64 * 64];
    __shared__ float sz1[64 * 128];
    __shared__ float sz2[64 * 32];
    int t = threadIdx.x;
    for (int i = t; i < 64 * 64; i += 128) {
        int gph = i >> 6;
        float c = g_cnt[gph];
        sp[i] = g_pool[i] / fmaxf(c, 1.0f);
    }
    __syncthreads();
    for (int i = t; i < 64 * 128; i += 128) {
        int gph = i >> 7, j = i & 127;
        float a = fb1[j];
        for (int f = 0; f < 64; f++) a += sp[gph * 64 + f] * fw1[f * 128 + j];
        sz1[i] = lrelu2(a);
    }
    __syncthreads();
    for (int i = t; i < 64 * 32; i += 128) {
        int gph = i >> 5, j = i & 31;
        float a = fb2[j];
        for (int f = 0; f < 128; f++) a += sz1[gph * 128 + f] * fw2[f * 32 + j];
        sz2[i] = lrelu2(a);
    }
    __syncthreads();
    for (int i = t; i < 64 * 2; i += 128) {
        int gph = i >> 1, j = i & 1;
        float a = fb3[j];
        for (int f = 0; f < 32; f++) a += sz2[gph * 32 + f] * fw3[f * 2 + j];
        out[i] = a;
    }
}

// ---------------- host launcher ----------------
extern "C" void kernel_launch(void* const* d_in, const int* in_sizes, int n_in,
                              void* d_out, int out_size) {
    const float* x     = (const float*)d_in[0];
    const int*   ei    = (const int*)d_in[1];
    const int*   batch = (const int*)d_in[2];
    const float* W1  = (const float*)d_in[3];
    const float* as1 = (const float*)d_in[4];
    const float* ad1 = (const float*)d_in[5];
    const float* b1  = (const float*)d_in[6];
    const float* W2  = (const float*)d_in[7];
    const float* as2 = (const float*)d_in[8];
    const float* ad2 = (const float*)d_in[9];
    const float* b2  = (const float*)d_in[10];
    const float* W3  = (const float*)d_in[11];
    const float* as3 = (const float*)d_in[12];
    const float* ad3 = (const float*)d_in[13];
    const float* b3  = (const float*)d_in[14];
    const float* g1  = (const float*)d_in[15];
    const float* bt1 = (const float*)d_in[16];
    const float* g2  = (const float*)d_in[17];
    const float* bt2 = (const float*)d_in[18];
    const float* g3  = (const float*)d_in[19];
    const float* bt3 = (const float*)d_in[20];
    const float* fw1 = (const float*)d_in[21];
    const float* fb1 = (const float*)d_in[22];
    const float* fw2 = (const float*)d_in[23];
    const float* fb2 = (const float*)d_in[24];
    const float* fw3 = (const float*)d_in[25];
    const float* fb3 = (const float*)d_in[26];

    int N = in_sizes[0] / 128;
    int E = in_sizes[1] / 2;
    int ET = E + N;

    float *ph, *po, *pas, *pad;
    cudaGetSymbolAddress((void**)&ph,  g_h);
    cudaGetSymbolAddress((void**)&po,  g_o);
    cudaGetSymbolAddress((void**)&pas, g_as);
    cudaGetSymbolAddress((void**)&pad, g_ad);

    int wblocks = (N * 32 + 255) / 256;
    int nblocks = (N + 7) / 8;
    int mblocks = (N + 127) / 128;

    kzero_deg<<<(N + 255) / 256, 256>>>(N);
    khist<<<(ET + 255) / 256, 256>>>(ei, E, N);
    kscan<<<1, 1024>>>(N);
    tgemm<128, false><<<dim3(2, mblocks), 256>>>(x, W1, ph, N, 256, 128, nullptr, nullptr);
    kscatter<<<(ET + 255) / 256, 256>>>(ei, E, N);

    // ---- layer 1: 128 -> 4x64 ----
    kscores<256, 4><<<wblocks, 256>>>(ph, as1, ad1, pas, pad, N);
    kmsg<256, 4><<<nblocks, 256>>>(ph, pas, pad, b1, po, N);

    // ---- layer 2: 256 -> 4x32 (BN+ELU fused into A-load) ----
    tgemm<128, true><<<dim3(1, mblocks), 256>>>(po, W2, ph, N, 128, 256, g1, bt1);
    kscores<128, 4><<<wblocks, 256>>>(ph, as2, ad2, pas, pad, N);
    kmsg<128, 4><<<nblocks, 256>>>(ph, pas, pad, b2, po, N);

    // ---- layer 3: 128 -> 1x64 (BN+ELU fused into A-load) ----
    tgemm<64, true><<<dim3(1, mblocks), 256>>>(po, W3, ph, N, 64, 128, g2, bt2);
    kscores<64, 1><<<wblocks, 256>>>(ph, as3, ad3, pas, pad, N);
    kmsg<64, 1><<<nblocks, 256>>>(ph, pas, pad, b3, po, N);

    // ---- pool (BN+ELU inline) + MLP ----
    kpool<<<(N * 64 + 255) / 256, 256>>>(po, batch, g3, bt3, N);
    kmlp<<<1, 128>>>(fw1, fb1, fw2, fb2, fw3, fb3, (float*)d_out);
}

// round 10
// speedup vs baseline: 1.0619x; 1.0089x over previous
#include <cuda_runtime.h>
#include <math.h>
#include <stdint.h>

// ---------------- static scratch (no allocations allowed) ----------------
#define MAXN 50000
#define MAXE 800000
#define MAXT (MAXN + MAXE)

__device__ int   g_deg[MAXN];
__device__ int   g_off[MAXN + 1];
__device__ int   g_cur[MAXN];
__device__ int   g_srcl[MAXT];
__device__ __align__(16) float g_h[(size_t)MAXN * 256];
__device__ __align__(16) float g_o[(size_t)MAXN * 256];
__device__ __align__(16) float g_as[MAXN * 4];
__device__ __align__(16) float g_ad[MAXN * 4];
__device__ float g_bnsum[256];
__device__ float g_bnsq[256];
__device__ float g_pool[64 * 64];
__device__ float g_cnt[64];

__device__ __forceinline__ float lrelu2(float v) { return v > 0.f ? v : 0.2f * v; }
__device__ __forceinline__ float eluf(float v) { return v > 0.f ? v : (__expf(v) - 1.0f); }
__device__ __forceinline__ unsigned f2tf(float x) {
    unsigned r;
    asm("cvt.rna.tf32.f32 %0, %1;" : "=r"(r) : "f"(x));
    return r;
}

// ---------------- CSR build ----------------
__global__ void kzero_deg(int N) {
    int i = blockIdx.x * blockDim.x + threadIdx.x;
    if (i < N) g_deg[i] = 0;
    if (i < 64 * 64) g_pool[i] = 0.f;
    if (i < 64) g_cnt[i] = 0.f;
}

__global__ void khist(const int* __restrict__ ei, int E, int N) {
    int i = blockIdx.x * blockDim.x + threadIdx.x;
    int T = E + N;
    if (i >= T) return;
    int d = (i < E) ? ei[E + i] : (i - E);
    atomicAdd(&g_deg[d], 1);
}

__global__ void kscan(int N) {
    __shared__ int sh[1024];
    int t = threadIdx.x;
    int chunk = (N + 1023) >> 10;
    int b = t * chunk;
    int e = min(b + chunk, N);
    int s = 0;
    for (int i = b; i < e; i++) s += g_deg[i];
    sh[t] = s;
    __syncthreads();
    for (int off = 1; off < 1024; off <<= 1) {
        int v = (t >= off) ? sh[t - off] : 0;
        __syncthreads();
        sh[t] += v;
        __syncthreads();
    }
    int run = (t == 0) ? 0 : sh[t - 1];
    for (int i = b; i < e; i++) {
        g_off[i] = run;
        g_cur[i] = run;
        run += g_deg[i];
    }
    if (t == 1023) g_off[N] = sh[1023];
}

__global__ void kscatter(const int* __restrict__ ei, int E, int N) {
    int i = blockIdx.x * blockDim.x + threadIdx.x;
    int T = E + N;
    if (i >= T) return;
    int s, d;
    if (i < E) { s = ei[i]; d = ei[E + i]; }
    else       { s = i - E; d = i - E; }
    int pos = atomicAdd(&g_cur[d], 1);
    g_srcl[pos] = s;
}

// ---------------- TF32 tensor-core GEMM: C[M,NT] = A[M,K] @ B[K,NT] (fp32 out) ----------------
template <int BN_, bool FUSE>
__global__ __launch_bounds__(256, 2) void tgemm(
    const float* __restrict__ A, const float* __restrict__ B, float* __restrict__ C,
    int M, int NT, int K,
    const float* __restrict__ gam, const float* __restrict__ bet)
{
    constexpr int BM_ = 128, BK_ = 32;
    constexpr int RA = BK_ + 4;
    constexpr int RB = BN_ + 8;
    constexpr int NU = BN_ / 32;
    constexpr int NBF = BK_ * BN_ / 4 / 256;

    __shared__ unsigned sA[BM_ * RA];
    __shared__ unsigned sB[BK_ * RB];
    __shared__ float ssc[256], ssh[256];

    const int t = threadIdx.x;
    const int lane = t & 31;
    const int wid = t >> 5;
    const int wr = wid >> 2;
    const int wc = wid & 3;
    const int rowBase = blockIdx.y * BM_;
    const int colBase = blockIdx.x * BN_;
    const int mmarow = lane >> 2;
    const int mmak = lane & 3;

    if (FUSE) {
        float invN = 1.0f / (float)M;
        for (int i = t; i < K; i += 256) {
            float mean = g_bnsum[i] * invN;
            float var = g_bnsq[i] * invN - mean * mean;
            float s = rsqrtf(var + 1e-5f) * gam[i];
            ssc[i] = s;
            ssh[i] = bet[i] - mean * s;
        }
    }

    float acc[4][NU][4];
#pragma unroll
    for (int m = 0; m < 4; m++)
#pragma unroll
        for (int u = 0; u < NU; u++)
#pragma unroll
            for (int j = 0; j < 4; j++) acc[m][u][j] = 0.f;

    for (int k0 = 0; k0 < K; k0 += BK_) {
        __syncthreads();
#pragma unroll
        for (int i = 0; i < 4; i++) {
            int f = i * 256 + t;
            int row = f >> 3;
            int c4 = (f & 7) << 2;
            int gr = rowBase + row;
            float4 v = make_float4(0.f, 0.f, 0.f, 0.f);
            if (gr < M) v = *(const float4*)&A[(size_t)gr * K + k0 + c4];
            if (FUSE) {
                int c = k0 + c4;
                v.x = eluf(v.x * ssc[c + 0] + ssh[c + 0]);
                v.y = eluf(v.y * ssc[c + 1] + ssh[c + 1]);
                v.z = eluf(v.z * ssc[c + 2] + ssh[c + 2]);
                v.w = eluf(v.w * ssc[c + 3] + ssh[c + 3]);
            }
            uint4 w = make_uint4(f2tf(v.x), f2tf(v.y), f2tf(v.z), f2tf(v.w));
            *(uint4*)&sA[row * RA + c4] = w;
        }
#pragma unroll
        for (int i = 0; i < NBF; i++) {
            int f = i * 256 + t;
            int krow = f / (BN_ / 4);
            int c4 = (f % (BN_ / 4)) << 2;
            float4 v = *(const float4*)&B[(size_t)(k0 + krow) * NT + colBase + c4];
            uint4 w = make_uint4(f2tf(v.x), f2tf(v.y), f2tf(v.z), f2tf(v.w));
            *(uint4*)&sB[krow * RB + c4] = w;
        }
        __syncthreads();

#pragma unroll
        for (int s = 0; s < 4; s++) {
            unsigned af[4][4], bf[NU][2];
            int ak = s * 8 + mmak;
#pragma unroll
            for (int m = 0; m < 4; m++) {
                int r = wr * 64 + m * 16 + mmarow;
                const unsigned* p = &sA[r * RA + ak];
                af[m][0] = p[0];
                af[m][1] = p[8 * RA];
                af[m][2] = p[4];
                af[m][3] = p[8 * RA + 4];
            }
#pragma unroll
            for (int u = 0; u < NU; u++) {
                int c = wc * (BN_ / 4) + u * 8 + mmarow;
                const unsigned* p = &sB[ak * RB + c];
                bf[u][0] = p[0];
                bf[u][1] = p[4 * RB];
            }
#pragma unroll
            for (int m = 0; m < 4; m++)
#pragma unroll
                for (int u = 0; u < NU; u++) {
                    asm volatile(
                        "mma.sync.aligned.m16n8k8.row.col.f32.tf32.tf32.f32 "
                        "{%0,%1,%2,%3}, {%4,%5,%6,%7}, {%8,%9}, {%0,%1,%2,%3};"
                        : "+f"(acc[m][u][0]), "+f"(acc[m][u][1]),
                          "+f"(acc[m][u][2]), "+f"(acc[m][u][3])
                        : "r"(af[m][0]), "r"(af[m][1]), "r"(af[m][2]), "r"(af[m][3]),
                          "r"(bf[u][0]), "r"(bf[u][1]));
                }
        }
    }

#pragma unroll
    for (int m = 0; m < 4; m++) {
        int r0 = rowBase + wr * 64 + m * 16 + mmarow;
#pragma unroll
        for (int u = 0; u < NU; u++) {
            int c = colBase + wc * (BN_ / 4) + u * 8 + mmak * 2;
            if (r0 < M)
                *(float2*)&C[(size_t)r0 * NT + c] = make_float2(acc[m][u][0], acc[m][u][1]);
            if (r0 + 8 < M)
                *(float2*)&C[(size_t)(r0 + 8) * NT + c] = make_float2(acc[m][u][2], acc[m][u][3]);
        }
    }
}

// ---------------- per-node attention scores (fp32, vectorized) + BN zeroing ----------------
template <int HC, int H>
__global__ __launch_bounds__(256) void kscores(const float* __restrict__ h,
                                               const float* __restrict__ atts,
                                               const float* __restrict__ attd,
                                               float* __restrict__ as_,
                                               float* __restrict__ ad_, int N) {
    if (blockIdx.x == 0 && threadIdx.x < 256) {
        g_bnsum[threadIdx.x] = 0.f;
        g_bnsq[threadIdx.x] = 0.f;
    }
    int w = (blockIdx.x * blockDim.x + threadIdx.x) >> 5;
    int lane = threadIdx.x & 31;
    if (w >= N) return;
    float aS = 0.f, aD = 0.f;
    if (HC == 256) {
        const float4* hr = (const float4*)&h[(size_t)w * 256];
        float4 v0 = hr[lane * 2], v1 = hr[lane * 2 + 1];
        int c0 = lane * 8;
        float4 s0 = *(const float4*)&atts[c0], s1 = *(const float4*)&atts[c0 + 4];
        float4 t0 = *(const float4*)&attd[c0], t1 = *(const float4*)&attd[c0 + 4];
        aS = v0.x * s0.x + v0.y * s0.y + v0.z * s0.z + v0.w * s0.w
           + v1.x * s1.x + v1.y * s1.y + v1.z * s1.z + v1.w * s1.w;
        aD = v0.x * t0.x + v0.y * t0.y + v0.z * t0.z + v0.w * t0.w
           + v1.x * t1.x + v1.y * t1.y + v1.z * t1.z + v1.w * t1.w;
    } else if (HC == 128) {
        const float4* hr = (const float4*)&h[(size_t)w * 128];
        float4 v = hr[lane];
        int c0 = lane * 4;
        float4 s = *(const float4*)&atts[c0];
        float4 t0 = *(const float4*)&attd[c0];
        aS = v.x * s.x + v.y * s.y + v.z * s.z + v.w * s.w;
        aD = v.x * t0.x + v.y * t0.y + v.z * t0.z + v.w * t0.w;
    } else {
        const float2* hr = (const float2*)&h[(size_t)w * 64];
        float2 v = hr[lane];
        int c0 = lane * 2;
        aS = v.x * atts[c0] + v.y * atts[c0 + 1];
        aD = v.x * attd[c0] + v.y * attd[c0 + 1];
    }
    if (H == 4) {
#pragma unroll
        for (int o = 4; o > 0; o >>= 1) {
            aS += __shfl_xor_sync(0xffffffffu, aS, o);
            aD += __shfl_xor_sync(0xffffffffu, aD, o);
        }
        if ((lane & 7) == 0) {
            int hh = lane >> 3;
            as_[w * 4 + hh] = aS;
            ad_[w * 4 + hh] = aD;
        }
    } else {
#pragma unroll
        for (int o = 16; o > 0; o >>= 1) {
            aS += __shfl_xor_sync(0xffffffffu, aS, o);
            aD += __shfl_xor_sync(0xffffffffu, aD, o);
        }
        if (lane == 0) { as_[w] = aS; ad_[w] = aD; }
    }
}

// ---------------- SINGLE-PASS segment-softmax + aggregation + atomic-free BN stats ----------------
// __launch_bounds__(256,3): 24 warps/SM for more gathers in flight.
// srcl indices for the next 4-edge group are prefetched before computing the current group.
template <int HC, int H>
__global__ __launch_bounds__(256, 3) void kmsg(
    const float* __restrict__ h, const float* __restrict__ as_,
    const float* __restrict__ ad_, const float* __restrict__ bias,
    float* __restrict__ out, int N)
{
    __shared__ float sS[8 * HC], sQ[8 * HC];
    int t = threadIdx.x;
    for (int i = t; i < 8 * HC; i += 256) { sS[i] = 0.f; sQ[i] = 0.f; }
    __syncthreads();

    int wid = t >> 5;
    int lane = t & 31;
    int w = blockIdx.x * 8 + wid;

    if (w < N) {
        int beg = g_off[w], end = g_off[w + 1];

        float ad0 = 0.f, ad1 = 0.f, ad2 = 0.f, ad3 = 0.f;
        if (H == 4) {
            float4 v = *(const float4*)&ad_[w * 4];
            ad0 = v.x; ad1 = v.y; ad2 = v.z; ad3 = v.w;
        } else {
            ad0 = ad_[w];
        }

        if (HC == 256) {
            int hA = (lane < 16) ? 0 : 1;
            float dA = (lane < 16) ? ad0 : ad1;
            float dB = (lane < 16) ? ad2 : ad3;
            const float4* h4 = (const float4*)h;
            float4 acc0 = make_float4(0.f, 0.f, 0.f, 0.f);
            float4 acc1 = make_float4(0.f, 0.f, 0.f, 0.f);
            float denA = 0.f, denB = 0.f;
            int e = beg;
            int sn0 = 0, sn1 = 0, sn2 = 0, sn3 = 0;
            bool have = (e + 4 <= end);
            if (have) {
                sn0 = g_srcl[e]; sn1 = g_srcl[e + 1];
                sn2 = g_srcl[e + 2]; sn3 = g_srcl[e + 3];
            }
            while (have) {
                int s0 = sn0, s1 = sn1, s2 = sn2, s3 = sn3;
                e += 4;
                have = (e + 4 <= end);
                if (have) {
                    sn0 = g_srcl[e]; sn1 = g_srcl[e + 1];
                    sn2 = g_srcl[e + 2]; sn3 = g_srcl[e + 3];
                }
                float aA0 = as_[s0 * 4 + hA], aB0 = as_[s0 * 4 + hA + 2];
                float aA1 = as_[s1 * 4 + hA], aB1 = as_[s1 * 4 + hA + 2];
                float aA2 = as_[s2 * 4 + hA], aB2 = as_[s2 * 4 + hA + 2];
                float aA3 = as_[s3 * 4 + hA], aB3 = as_[s3 * 4 + hA + 2];
                float4 f00 = h4[(size_t)s0 * 64 + lane];
                float4 f01 = h4[(size_t)s0 * 64 + 32 + lane];
                float4 f10 = h4[(size_t)s1 * 64 + lane];
                float4 f11 = h4[(size_t)s1 * 64 + 32 + lane];
                float4 f20 = h4[(size_t)s2 * 64 + lane];
                float4 f21 = h4[(size_t)s2 * 64 + 32 + lane];
                float4 f30 = h4[(size_t)s3 * 64 + lane];
                float4 f31 = h4[(size_t)s3 * 64 + 32 + lane];
                float lA0 = __expf(lrelu2(aA0 + dA)), lB0 = __expf(lrelu2(aB0 + dB));
                float lA1 = __expf(lrelu2(aA1 + dA)), lB1 = __expf(lrelu2(aB1 + dB));
                float lA2 = __expf(lrelu2(aA2 + dA)), lB2 = __expf(lrelu2(aB2 + dB));
                float lA3 = __expf(lrelu2(aA3 + dA)), lB3 = __expf(lrelu2(aB3 + dB));
                denA += lA0 + lA1 + lA2 + lA3;
                denB += lB0 + lB1 + lB2 + lB3;
                acc0.x += f00.x * lA0; acc0.y += f00.y * lA0; acc0.z += f00.z * lA0; acc0.w += f00.w * lA0;
                acc1.x += f01.x * lB0; acc1.y += f01.y * lB0; acc1.z += f01.z * lB0; acc1.w += f01.w * lB0;
                acc0.x += f10.x * lA1; acc0.y += f10.y * lA1; acc0.z += f10.z * lA1; acc0.w += f10.w * lA1;
                acc1.x += f11.x * lB1; acc1.y += f11.y * lB1; acc1.z += f11.z * lB1; acc1.w += f11.w * lB1;
                acc0.x += f20.x * lA2; acc0.y += f20.y * lA2; acc0.z += f20.z * lA2; acc0.w += f20.w * lA2;
                acc1.x += f21.x * lB2; acc1.y += f21.y * lB2; acc1.z += f21.z * lB2; acc1.w += f21.w * lB2;
                acc0.x += f30.x * lA3; acc0.y += f30.y * lA3; acc0.z += f30.z * lA3; acc0.w += f30.w * lA3;
                acc1.x += f31.x * lB3; acc1.y += f31.y * lB3; acc1.z += f31.z * lB3; acc1.w += f31.w * lB3;
            }
            for (; e < end; e++) {
                int s = g_srcl[e];
                float aA = as_[s * 4 + hA], aB = as_[s * 4 + hA + 2];
                float4 f0 = h4[(size_t)s * 64 + lane];
                float4 f1 = h4[(size_t)s * 64 + 32 + lane];
                float lA = __expf(lrelu2(aA + dA)), lB = __expf(lrelu2(aB + dB));
                denA += lA; denB += lB;
                acc0.x += f0.x * lA; acc0.y += f0.y * lA; acc0.z += f0.z * lA; acc0.w += f0.w * lA;
                acc1.x += f1.x * lB; acc1.y += f1.y * lB; acc1.z += f1.z * lB; acc1.w += f1.w * lB;
            }
            float rA = 1.0f / (denA + 1e-16f);
            float rB = 1.0f / (denB + 1e-16f);
            int c0 = lane * 4;
            float4 b0 = *(const float4*)&bias[c0];
            float4 b1 = *(const float4*)&bias[128 + c0];
            float4 v0 = make_float4(acc0.x * rA + b0.x, acc0.y * rA + b0.y,
                                    acc0.z * rA + b0.z, acc0.w * rA + b0.w);
            float4 v1 = make_float4(acc1.x * rB + b1.x, acc1.y * rB + b1.y,
                                    acc1.z * rB + b1.z, acc1.w * rB + b1.w);
            float* orow = &out[(size_t)w * 256];
            *(float4*)&orow[c0] = v0;
            *(float4*)&orow[128 + c0] = v1;
            *(float4*)&sS[wid * 256 + c0] = v0;
            *(float4*)&sS[wid * 256 + 128 + c0] = v1;
            *(float4*)&sQ[wid * 256 + c0] =
                make_float4(v0.x * v0.x, v0.y * v0.y, v0.z * v0.z, v0.w * v0.w);
            *(float4*)&sQ[wid * 256 + 128 + c0] =
                make_float4(v1.x * v1.x, v1.y * v1.y, v1.z * v1.z, v1.w * v1.w);
        } else if (HC == 128) {
            int hs = lane >> 3;
            float dh = hs == 0 ? ad0 : hs == 1 ? ad1 : hs == 2 ? ad2 : ad3;
            const float4* h4 = (const float4*)h;
            float4 acc = make_float4(0.f, 0.f, 0.f, 0.f);
            float den = 0.f;
            int e = beg;
            int sn0 = 0, sn1 = 0, sn2 = 0, sn3 = 0;
            bool have = (e + 4 <= end);
            if (have) {
                sn0 = g_srcl[e]; sn1 = g_srcl[e + 1];
                sn2 = g_srcl[e + 2]; sn3 = g_srcl[e + 3];
            }
            while (have) {
                int s0 = sn0, s1 = sn1, s2 = sn2, s3 = sn3;
                e += 4;
                have = (e + 4 <= end);
                if (have) {
                    sn0 = g_srcl[e]; sn1 = g_srcl[e + 1];
                    sn2 = g_srcl[e + 2]; sn3 = g_srcl[e + 3];
                }
                float a0 = as_[s0 * 4 + hs];
                float a1 = as_[s1 * 4 + hs];
                float a2 = as_[s2 * 4 + hs];
                float a3 = as_[s3 * 4 + hs];
                float4 f0 = h4[(size_t)s0 * 32 + lane];
                float4 f1 = h4[(size_t)s1 * 32 + lane];
                float4 f2 = h4[(size_t)s2 * 32 + lane];
                float4 f3 = h4[(size_t)s3 * 32 + lane];
                float l0 = __expf(lrelu2(a0 + dh));
                float l1 = __expf(lrelu2(a1 + dh));
                float l2 = __expf(lrelu2(a2 + dh));
                float l3 = __expf(lrelu2(a3 + dh));
                den += l0 + l1 + l2 + l3;
                acc.x += f0.x * l0; acc.y += f0.y * l0; acc.z += f0.z * l0; acc.w += f0.w * l0;
                acc.x += f1.x * l1; acc.y += f1.y * l1; acc.z += f1.z * l1; acc.w += f1.w * l1;
                acc.x += f2.x * l2; acc.y += f2.y * l2; acc.z += f2.z * l2; acc.w += f2.w * l2;
                acc.x += f3.x * l3; acc.y += f3.y * l3; acc.z += f3.z * l3; acc.w += f3.w * l3;
            }
            for (; e < end; e++) {
                int s = g_srcl[e];
                float a = as_[s * 4 + hs];
                float4 f = h4[(size_t)s * 32 + lane];
                float l = __expf(lrelu2(a + dh));
                den += l;
                acc.x += f.x * l; acc.y += f.y * l; acc.z += f.z * l; acc.w += f.w * l;
            }
            float rh = 1.0f / (den + 1e-16f);
            int c0 = lane * 4;
            float4 b = *(const float4*)&bias[c0];
            float4 v = make_float4(acc.x * rh + b.x, acc.y * rh + b.y,
                                   acc.z * rh + b.z, acc.w * rh + b.w);
            *(float4*)&out[(size_t)w * 128 + c0] = v;
            *(float4*)&sS[wid * 128 + c0] = v;
            *(float4*)&sQ[wid * 128 + c0] =
                make_float4(v.x * v.x, v.y * v.y, v.z * v.z, v.w * v.w);
        } else { // HC == 64, H == 1
            const float2* h2 = (const float2*)h;
            float ax = 0.f, ay = 0.f, den = 0.f;
            int e = beg;
            int sn0 = 0, sn1 = 0, sn2 = 0, sn3 = 0;
            bool have = (e + 4 <= end);
            if (have) {
                sn0 = g_srcl[e]; sn1 = g_srcl[e + 1];
                sn2 = g_srcl[e + 2]; sn3 = g_srcl[e + 3];
            }
            while (have) {
                int s0 = sn0, s1 = sn1, s2 = sn2, s3 = sn3;
                e += 4;
                have = (e + 4 <= end);
                if (have) {
                    sn0 = g_srcl[e]; sn1 = g_srcl[e + 1];
                    sn2 = g_srcl[e + 2]; sn3 = g_srcl[e + 3];
                }
                float a0 = as_[s0], a1 = as_[s1], a2 = as_[s2], a3 = as_[s3];
                float2 f0 = h2[(size_t)s0 * 32 + lane];
                float2 f1 = h2[(size_t)s1 * 32 + lane];
                float2 f2 = h2[(size_t)s2 * 32 + lane];
                float2 f3 = h2[(size_t)s3 * 32 + lane];
                float l0 = __expf(lrelu2(a0 + ad0));
                float l1 = __expf(lrelu2(a1 + ad0));
                float l2 = __expf(lrelu2(a2 + ad0));
                float l3 = __expf(lrelu2(a3 + ad0));
                den += l0 + l1 + l2 + l3;
                ax += f0.x * l0; ay += f0.y * l0;
                ax += f1.x * l1; ay += f1.y * l1;
                ax += f2.x * l2; ay += f2.y * l2;
                ax += f3.x * l3; ay += f3.y * l3;
            }
            for (; e < end; e++) {
                int s = g_srcl[e];
                float a = as_[s];
                float2 f = h2[(size_t)s * 32 + lane];
                float l = __expf(lrelu2(a + ad0));
                den += l;
                ax += f.x * l; ay += f.y * l;
            }
            float r0 = 1.0f / (den + 1e-16f);
            int c0 = lane * 2;
            float v0 = ax * r0 + bias[c0];
            float v1 = ay * r0 + bias[c0 + 1];
            *(float2*)&out[(size_t)w * 64 + c0] = make_float2(v0, v1);
            *(float2*)&sS[wid * 64 + c0] = make_float2(v0, v1);
            *(float2*)&sQ[wid * 64 + c0] = make_float2(v0 * v0, v1 * v1);
        }
    }
    __syncthreads();
    if (t < HC) {
        float s = 0.f, q = 0.f;
#pragma unroll
        for (int wpb = 0; wpb < 8; wpb++) {
            s += sS[wpb * HC + t];
            q += sQ[wpb * HC + t];
        }
        atomicAdd(&g_bnsum[t], s);
        atomicAdd(&g_bnsq[t], q);
    }
}

// ---------------- global mean pool (BN+ELU inline) + MLP ----------------
__global__ void kpool(const float* __restrict__ hfin, const int* __restrict__ batch,
                      const float* __restrict__ gam, const float* __restrict__ bet, int N) {
    __shared__ float ssc[64], ssh[64];
    if (threadIdx.x < 64) {
        int f = threadIdx.x;
        float invN = 1.0f / (float)N;
        float mean = g_bnsum[f] * invN;
        float var = g_bnsq[f] * invN - mean * mean;
        float s = rsqrtf(var + 1e-5f) * gam[f];
        ssc[f] = s;
        ssh[f] = bet[f] - mean * s;
    }
    __syncthreads();
    int i = blockIdx.x * blockDim.x + threadIdx.x;
    if (i >= N * 64) return;
    int n = i >> 6, f = i & 63;
    float v = hfin[i] * ssc[f] + ssh[f];
    v = v > 0.f ? v : (__expf(v) - 1.0f);
    int gph = batch[n];
    atomicAdd(&g_pool[gph * 64 + f], v);
    if (f == 0) atomicAdd(&g_cnt[gph], 1.0f);
}

__global__ __launch_bounds__(128) void kmlp(const float* __restrict__ fw1, const float* __restrict__ fb1,
                                            const float* __restrict__ fw2, const float* __restrict__ fb2,
                                            const float* __restrict__ fw3, const float* __restrict__ fb3,
                                            float* __restrict__ out) {
    __shared__ float sp[64 * 64];
    __shared__ float sz1[64 * 128];
    __shared__ float sz2[64 * 32];
    int t = threadIdx.x;
    for (int i = t; i < 64 * 64; i += 128) {
        int gph = i >> 6;
        float c = g_cnt[gph];
        sp[i] = g_pool[i] / fmaxf(c, 1.0f);
    }
    __syncthreads();
    for (int i = t; i < 64 * 128; i += 128) {
        int gph = i >> 7, j = i & 127;
        float a = fb1[j];
        for (int f = 0; f < 64; f++) a += sp[gph * 64 + f] * fw1[f * 128 + j];
        sz1[i] = lrelu2(a);
    }
    __syncthreads();
    for (int i = t; i < 64 * 32; i += 128) {
        int gph = i >> 5, j = i & 31;
        float a = fb2[j];
        for (int f = 0; f < 128; f++) a += sz1[gph * 128 + f] * fw2[f * 32 + j];
        sz2[i] = lrelu2(a);
    }
    __syncthreads();
    for (int i = t; i < 64 * 2; i += 128) {
        int gph = i >> 1, j = i & 1;
        float a = fb3[j];
        for (int f = 0; f < 32; f++) a += sz2[gph * 32 + f] * fw3[f * 2 + j];
        out[i] = a;
    }
}

// ---------------- host launcher ----------------
extern "C" void kernel_launch(void* const* d_in, const int* in_sizes, int n_in,
                              void* d_out, int out_size) {
    const float* x     = (const float*)d_in[0];
    const int*   ei    = (const int*)d_in[1];
    const int*   batch = (const int*)d_in[2];
    const float* W1  = (const float*)d_in[3];
    const float* as1 = (const float*)d_in[4];
    const float* ad1 = (const float*)d_in[5];
    const float* b1  = (const float*)d_in[6];
    const float* W2  = (const float*)d_in[7];
    const float* as2 = (const float*)d_in[8];
    const float* ad2 = (const float*)d_in[9];
    const float* b2  = (const float*)d_in[10];
    const float* W3  = (const float*)d_in[11];
    const float* as3 = (const float*)d_in[12];
    const float* ad3 = (const float*)d_in[13];
    const float* b3  = (const float*)d_in[14];
    const float* g1  = (const float*)d_in[15];
    const float* bt1 = (const float*)d_in[16];
    const float* g2  = (const float*)d_in[17];
    const float* bt2 = (const float*)d_in[18];
    const float* g3  = (const float*)d_in[19];
    const float* bt3 = (const float*)d_in[20];
    const float* fw1 = (const float*)d_in[21];
    const float* fb1 = (const float*)d_in[22];
    const float* fw2 = (const float*)d_in[23];
    const float* fb2 = (const float*)d_in[24];
    const float* fw3 = (const float*)d_in[25];
    const float* fb3 = (const float*)d_in[26];

    int N = in_sizes[0] / 128;
    int E = in_sizes[1] / 2;
    int ET = E + N;

    float *ph, *po, *pas, *pad;
    cudaGetSymbolAddress((void**)&ph,  g_h);
    cudaGetSymbolAddress((void**)&po,  g_o);
    cudaGetSymbolAddress((void**)&pas, g_as);
    cudaGetSymbolAddress((void**)&pad, g_ad);

    int wblocks = (N * 32 + 255) / 256;
    int nblocks = (N + 7) / 8;
    int mblocks = (N + 127) / 128;

    kzero_deg<<<(N + 255) / 256, 256>>>(N);
    khist<<<(ET + 255) / 256, 256>>>(ei, E, N);
    kscan<<<1, 1024>>>(N);
    tgemm<128, false><<<dim3(2, mblocks), 256>>>(x, W1, ph, N, 256, 128, nullptr, nullptr);
    kscatter<<<(ET + 255) / 256, 256>>>(ei, E, N);

    // ---- layer 1: 128 -> 4x64 ----
    kscores<256, 4><<<wblocks, 256>>>(ph, as1, ad1, pas, pad, N);
    kmsg<256, 4><<<nblocks, 256>>>(ph, pas, pad, b1, po, N);

    // ---- layer 2: 256 -> 4x32 (BN+ELU fused into A-load) ----
    tgemm<128, true><<<dim3(1, mblocks), 256>>>(po, W2, ph, N, 128, 256, g1, bt1);
    kscores<128, 4><<<wblocks, 256>>>(ph, as2, ad2, pas, pad, N);
    kmsg<128, 4><<<nblocks, 256>>>(ph, pas, pad, b2, po, N);

    // ---- layer 3: 128 -> 1x64 (BN+ELU fused into A-load) ----
    tgemm<64, true><<<dim3(1, mblocks), 256>>>(po, W3, ph, N, 64, 128, g2, bt2);
    kscores<64, 1><<<wblocks, 256>>>(ph, as3, ad3, pas, pad, N);
    kmsg<64, 1><<<nblocks, 256>>>(ph, pas, pad, b3, po, N);

    // ---- pool (BN+ELU inline) + MLP ----
    kpool<<<(N * 64 + 255) / 256, 256>>>(po, batch, g3, bt3, N);
    kmlp<<<1, 128>>>(fw1, fb1, fw2, fb2, fw3, fb3, (float*)d_out);
}